// round 13
// baseline (speedup 1.0000x reference)
#include <cuda_runtime.h>
#include <cuda_bf16.h>
#include <cstdint>

// Shapes (fixed by the problem): N=8192 rows, D=128 feat, C=1000 classes.
#define N_MAX 8192
#define D_FIX 128
#define NBINS 1024
#define NCE_INV_T 10.0f
#define EPSV 1e-10f

#define TILE 128
#define ROWE 136                     // padded row stride (elements) -> 272 B
#define TILE_BYTES (TILE * ROWE * 2) // 34816 B per operand tile
#define SMEM_GEMM (2 * TILE_BYTES)   // 69632 B

#define MCAP 160                     // max class size handled in smem fast path
#define SMEM_POS (MCAP * 33 * 16 + 2 * 512 + MCAP * 4 + 64)

// ---------------- device scratch (no allocations allowed) ----------------
__device__ float  g_f1[N_MAX * D_FIX];   // normalized fs * 10 (fp32, for k_pos)
__device__ float  g_f2[N_MAX * D_FIX];   // normalized ft (fp32, for k_pos)
__device__ __align__(16) __nv_bfloat16 g_a16[N_MAX * ROWE]; // bf16 A, padded rows
__device__ __align__(16) __nv_bfloat16 g_b16[N_MAX * ROWE]; // bf16 B, padded rows
__device__ float  g_S1[N_MAX], g_S2[N_MAX], g_S3[N_MAX]; // row sums of e, e^2, e^3
__device__ int    g_tgt[N_MAX];
__device__ int    g_cnt[NBINS], g_off[NBINS], g_cur[NBINS];
__device__ int    g_sorted[N_MAX];
__device__ int    g_is64;
__device__ double g_acc;

// ---------------- PTX helpers ----------------
__device__ __forceinline__ uint32_t smem_to_u32(const void* p) {
    uint32_t a;
    asm("{ .reg .u64 t; cvta.to.shared.u64 t, %1; cvt.u32.u64 %0, t; }" : "=r"(a) : "l"(p));
    return a;
}
__device__ __forceinline__ void cp16(uint32_t dst, const void* src) {
    asm volatile("cp.async.cg.shared.global [%0], [%1], 16;" :: "r"(dst), "l"(src) : "memory");
}
__device__ __forceinline__ void ldsm_x4(uint32_t* r, uint32_t addr) {
    asm volatile("ldmatrix.sync.aligned.m8n8.x4.shared.b16 {%0,%1,%2,%3}, [%4];"
                 : "=r"(r[0]), "=r"(r[1]), "=r"(r[2]), "=r"(r[3]) : "r"(addr));
}
__device__ __forceinline__ void mma16816(float* c, const uint32_t* a, const uint32_t* b) {
    asm volatile("mma.sync.aligned.m16n8k16.row.col.f32.bf16.bf16.f32 "
                 "{%0,%1,%2,%3}, {%4,%5,%6,%7}, {%8,%9}, {%0,%1,%2,%3};"
                 : "+f"(c[0]), "+f"(c[1]), "+f"(c[2]), "+f"(c[3])
                 : "r"(a[0]), "r"(a[1]), "r"(a[2]), "r"(a[3]), "r"(b[0]), "r"(b[1]));
}

// ---------------- K0: zero accumulators (fresh every replay) ----------------
__global__ void k_init() {
    int i = blockIdx.x * blockDim.x + threadIdx.x;
    if (i < N_MAX) { g_S1[i] = 0.f; g_S2[i] = 0.f; g_S3[i] = 0.f; }
    if (i < NBINS) { g_cnt[i] = 0; g_cur[i] = 0; }
    if (i == 0) g_acc = 0.0;
}

// ---------------- K0b: detect target dtype (int64 vs int32) ------------------
__global__ void k_detect(const int* __restrict__ w) {
    int nz = 0;
    for (int i = threadIdx.x; i < 64; i += 32)
        if (w[2 * i + 1] != 0) nz = 1;
    #pragma unroll
    for (int o = 16; o; o >>= 1) nz |= __shfl_xor_sync(0xffffffffu, nz, o);
    if (threadIdx.x == 0) g_is64 = nz ? 0 : 1;
}

// ---------------- K1: normalize; fp32 copies + padded bf16 operands ----------
__global__ void k_prep(const float* __restrict__ fs, const float* __restrict__ ft, int N) {
    int row = blockIdx.x;
    bool is_s = (row < N);
    int r = is_s ? row : row - N;
    int k = threadIdx.x;
    const float* src = is_s ? fs : ft;
    float v = src[r * D_FIX + k];
    float ss = v * v;
    #pragma unroll
    for (int o = 16; o; o >>= 1) ss += __shfl_xor_sync(0xffffffffu, ss, o);
    __shared__ float ws[4];
    if ((k & 31) == 0) ws[k >> 5] = ss;
    __syncthreads();
    float tot = ws[0] + ws[1] + ws[2] + ws[3];
    float nrm = fmaxf(sqrtf(tot), 1e-12f);
    float x = v * ((is_s ? NCE_INV_T : 1.0f) / nrm);
    (is_s ? g_f1 : g_f2)[r * D_FIX + k] = x;
    __nv_bfloat16* dst = is_s ? g_a16 : g_b16;
    dst[r * ROWE + k] = __float2bfloat16(x);
    if (k < ROWE - D_FIX) dst[r * ROWE + D_FIX + k] = __float2bfloat16(0.f); // pad
}

// ---------------- K5: bf16 mma.sync GEMM + fused exp power sums ---------------
// 128x128 tile/CTA, 8 warps (4m x 2n -> 32x64 warp tiles), K=128 resident.
__global__ __launch_bounds__(256, 2) void k_gemm() {
    extern __shared__ __align__(16) unsigned char smem[];
    uint32_t SAu = smem_to_u32(smem);
    uint32_t SBu = SAu + TILE_BYTES;
    int tid = threadIdx.x, lane = tid & 31, wid = tid >> 5;
    int wm = wid & 3, wn = wid >> 2;
    int row0 = blockIdx.y * TILE, col0 = blockIdx.x * TILE;

    const char* ga = (const char*)(g_a16 + (size_t)row0 * ROWE);
    const char* gb = (const char*)(g_b16 + (size_t)col0 * ROWE);
    for (int o = tid; o < TILE_BYTES / 16; o += 256) {
        cp16(SAu + o * 16, ga + o * 16);
        cp16(SBu + o * 16, gb + o * 16);
    }
    asm volatile("cp.async.commit_group;" ::: "memory");
    asm volatile("cp.async.wait_group 0;" ::: "memory");
    __syncthreads();

    uint32_t a_base = SAu + (wm * 32 + (lane & 15)) * 272 + (((lane >> 4) & 1) << 3) * 2;
    uint32_t b_base = SBu + (wn * 64 + (((lane >> 4) & 1) << 3) + (lane & 7)) * 272
                          + (((lane >> 3) & 1) << 3) * 2;

    float c[2][8][4];
    #pragma unroll
    for (int mi = 0; mi < 2; mi++)
        #pragma unroll
        for (int ni = 0; ni < 8; ni++)
            #pragma unroll
            for (int j = 0; j < 4; j++) c[mi][ni][j] = 0.f;

    #pragma unroll
    for (int kb = 0; kb < 128; kb += 16) {
        uint32_t a[2][4], b[8][2];
        #pragma unroll
        for (int mi = 0; mi < 2; mi++)
            ldsm_x4(a[mi], a_base + mi * 16 * 272 + kb * 2);
        #pragma unroll
        for (int p = 0; p < 4; p++) {
            uint32_t r[4];
            ldsm_x4(r, b_base + p * 16 * 272 + kb * 2);
            b[2 * p][0] = r[0]; b[2 * p][1] = r[1];
            b[2 * p + 1][0] = r[2]; b[2 * p + 1][1] = r[3];
        }
        #pragma unroll
        for (int mi = 0; mi < 2; mi++)
            #pragma unroll
            for (int ni = 0; ni < 8; ni++)
                mma16816(c[mi][ni], a[mi], b[ni]);
    }

    // epilogue: e = exp(logit); per-row power sums (each thread owns 4 rows)
    float s1[4] = {0, 0, 0, 0}, s2[4] = {0, 0, 0, 0}, s3[4] = {0, 0, 0, 0};
    #pragma unroll
    for (int mi = 0; mi < 2; mi++)
        #pragma unroll
        for (int ni = 0; ni < 8; ni++)
            #pragma unroll
            for (int j = 0; j < 4; j++) {
                float e = __expf(c[mi][ni][j]);
                int idx = mi * 2 + (j >> 1);
                float e2 = e * e;
                s1[idx] += e; s2[idx] += e2; s3[idx] += e2 * e;
            }
    #pragma unroll
    for (int idx = 0; idx < 4; idx++) {
        #pragma unroll
        for (int o = 1; o <= 2; o <<= 1) {
            s1[idx] += __shfl_xor_sync(0xffffffffu, s1[idx], o);
            s2[idx] += __shfl_xor_sync(0xffffffffu, s2[idx], o);
            s3[idx] += __shfl_xor_sync(0xffffffffu, s3[idx], o);
        }
    }
    if ((lane & 3) == 0) {
        int g = lane >> 2;
        #pragma unroll
        for (int idx = 0; idx < 4; idx++) {
            int mi = idx >> 1, half = idx & 1;
            int grow = row0 + wm * 32 + mi * 16 + half * 8 + g;
            atomicAdd(&g_S1[grow], s1[idx]);
            atomicAdd(&g_S2[grow], s2[idx]);
            atomicAdd(&g_S3[grow], s3[idx]);
        }
    }
}

// ---------------- K2: class histogram + dtype-aware load ----------------
__global__ void k_count(const int* __restrict__ w, int N) {
    int i = blockIdx.x * blockDim.x + threadIdx.x;
    if (i < N) {
        int c = g_is64 ? w[2 * i] : w[i];
        if (c < 0 || c >= NBINS) c = 0;
        g_tgt[i] = c;
        atomicAdd(&g_cnt[c], 1);
    }
}

// ---------------- K3: exclusive scan over class counts (1 block) -------------
__global__ void k_scan() {
    __shared__ int s[NBINS];
    int t = threadIdx.x;
    s[t] = g_cnt[t];
    __syncthreads();
    for (int off = 1; off < NBINS; off <<= 1) {
        int v = (t >= off) ? s[t - off] : 0;
        __syncthreads();
        s[t] += v;
        __syncthreads();
    }
    g_off[t] = s[t] - g_cnt[t];
}

// ---------------- K4: scatter row ids grouped by class ----------------
__global__ void k_scatter(int N) {
    int i = blockIdx.x * blockDim.x + threadIdx.x;
    if (i < N) {
        int c = g_tgt[i];
        int p = atomicAdd(&g_cur[c], 1);
        g_sorted[g_off[c] + p] = i;
    }
}

// ---------------- K6: per-CLASS pos-pair kernel -------------------------------
// One CTA per class. Stage the class's ~82 f2 rows in smem once (float4,
// stride 33 -> conflict-free), then loop rows TWO at a time; each thread owns
// one pos column j and computes both dots from one f2 read.
// Row loss: plog/pcnt + (1 + S2/(2Z^2) + S3/(3Z^3) - pos_series)/(N-pcnt).
__global__ __launch_bounds__(128) void k_pos(int N) {
    extern __shared__ __align__(16) unsigned char pshm[];
    float4* f2c = (float4*)pshm;                                   // MCAP*33
    float4* f1a = (float4*)(pshm + MCAP * 33 * 16);                // 32
    float4* f1b = (float4*)(pshm + MCAP * 33 * 16 + 512);          // 32
    int*    ids = (int*)  (pshm + MCAP * 33 * 16 + 1024);          // MCAP
    float*  red = (float*)(pshm + MCAP * 33 * 16 + 1024 + MCAP * 4); // 16
    int c = blockIdx.x;
    int m = g_cnt[c];
    if (m == 0) return;
    int base = g_off[c];
    int tid = threadIdx.x, lane = tid & 31, wrp = tid >> 5;
    bool fast = (m <= MCAP);

    if (fast) {
        for (int j = tid; j < m; j += 128) ids[j] = g_sorted[base + j];
        __syncthreads();
        for (int idx = tid; idx < m * 32; idx += 128) {
            int j = idx >> 5, q = idx & 31;
            f2c[j * 33 + q] = ((const float4*)(g_f2 + (size_t)ids[j] * D_FIX))[q];
        }
    }
    __syncthreads();

    for (int ii = 0; ii < m; ii += 2) {
        bool two = (ii + 1 < m);
        int i0 = fast ? ids[ii] : g_sorted[base + ii];
        int i1 = two ? (fast ? ids[ii + 1] : g_sorted[base + ii + 1]) : i0;
        if (tid < 32) {
            f1a[tid] = ((const float4*)(g_f1 + (size_t)i0 * D_FIX))[tid];
            f1b[tid] = ((const float4*)(g_f1 + (size_t)i1 * D_FIX))[tid];
        }
        __syncthreads();
        float invZ0 = 1.0f / g_S1[i0];
        float invZ1 = 1.0f / g_S1[i1];
        float pl0 = 0.f, se0 = 0.f, pl1 = 0.f, se1 = 0.f;
        for (int j = tid; j < m; j += 128) {
            float d0 = 0.f, d1 = 0.f;
            const float4* b4p = fast ? &f2c[j * 33]
                : (const float4*)(g_f2 + (size_t)g_sorted[base + j] * D_FIX);
            #pragma unroll
            for (int q = 0; q < 32; q++) {
                float4 b4 = b4p[q];
                float4 a0 = f1a[q], a1 = f1b[q];
                d0 += a0.x * b4.x + a0.y * b4.y + a0.z * b4.z + a0.w * b4.w;
                d1 += a1.x * b4.x + a1.y * b4.y + a1.z * b4.z + a1.w * b4.w;
            }
            float p0 = __expf(d0) * invZ0;
            pl0 -= __logf(p0 + EPSV);
            se0 += p0 * (1.f + p0 * (0.5f + p0 * (1.f / 3.f)));
            float p1 = __expf(d1) * invZ1;
            pl1 -= __logf(p1 + EPSV);
            se1 += p1 * (1.f + p1 * (0.5f + p1 * (1.f / 3.f)));
        }
        #pragma unroll
        for (int o = 16; o; o >>= 1) {
            pl0 += __shfl_xor_sync(0xffffffffu, pl0, o);
            se0 += __shfl_xor_sync(0xffffffffu, se0, o);
            pl1 += __shfl_xor_sync(0xffffffffu, pl1, o);
            se1 += __shfl_xor_sync(0xffffffffu, se1, o);
        }
        if (lane == 0) {
            red[wrp] = pl0; red[4 + wrp] = se0;
            red[8 + wrp] = pl1; red[12 + wrp] = se1;
        }
        __syncthreads();
        if (tid == 0) {
            float a0 = red[0] + red[1] + red[2] + red[3];
            float b0 = red[4] + red[5] + red[6] + red[7];
            float s2 = g_S2[i0] * invZ0 * invZ0;
            float s3 = g_S3[i0] * invZ0 * invZ0 * invZ0;
            float negs = 1.0f + 0.5f * s2 + (1.f / 3.f) * s3 - b0;
            double rs = (double)(a0 / (float)m + negs / (float)(N - m));
            if (two) {
                float a1 = red[8] + red[9] + red[10] + red[11];
                float b1 = red[12] + red[13] + red[14] + red[15];
                float t2 = g_S2[i1] * invZ1 * invZ1;
                float t3 = g_S3[i1] * invZ1 * invZ1 * invZ1;
                float ng1 = 1.0f + 0.5f * t2 + (1.f / 3.f) * t3 - b1;
                rs += (double)(a1 / (float)m + ng1 / (float)(N - m));
            }
            atomicAdd(&g_acc, rs / (double)N);
        }
        __syncthreads();
    }
}

// ---------------- K7: JSD rows, single pass -----------------------------------
// kl_st + kl_ts = sum (pt - ps)(log pt - log ps) = sum (pt - ps)(b - a)
// (the log-Z terms cancel since sum(pt - ps) = 0). One pass accumulates
// Zs, Zt, Sds = sum e^a (b-a), Sdt = sum e^b (b-a); kl = Sdt/Zt - Sds/Zs.
__global__ void k_jsd(const float* __restrict__ ls, const float* __restrict__ lt,
                      int N, int C) {
    int i = blockIdx.x;
    int tid = threadIdx.x; // 256
    const float* s = ls + (size_t)i * C;
    const float* t = lt + (size_t)i * C;
    float es = 0.f, et = 0.f, ds = 0.f, dt = 0.f;
    for (int j = tid; j < C; j += 256) {
        float a = s[j], b = t[j];
        float ea = __expf(a), eb = __expf(b);
        float d = b - a;
        es += ea; et += eb;
        ds += ea * d; dt += eb * d;
    }
    #pragma unroll
    for (int o = 16; o; o >>= 1) {
        es += __shfl_xor_sync(0xffffffffu, es, o);
        et += __shfl_xor_sync(0xffffffffu, et, o);
        ds += __shfl_xor_sync(0xffffffffu, ds, o);
        dt += __shfl_xor_sync(0xffffffffu, dt, o);
    }
    __shared__ float w1[8], w2[8], w3[8], w4[8];
    if ((tid & 31) == 0) {
        int w = tid >> 5;
        w1[w] = es; w2[w] = et; w3[w] = ds; w4[w] = dt;
    }
    __syncthreads();
    if (tid == 0) {
        float zs = 0.f, zt = 0.f, sd = 0.f, td = 0.f;
        #pragma unroll
        for (int w = 0; w < 8; w++) { zs += w1[w]; zt += w2[w]; sd += w3[w]; td += w4[w]; }
        float kl = td / zt - sd / zs;
        atomicAdd(&g_acc, 0.5 * (double)kl / (double)N);
    }
}

// ---------------- K8: write scalar output ----------------
__global__ void k_final(float* out) {
    if (threadIdx.x == 0) out[0] = (float)g_acc;
}

// ---------------- launcher ----------------
extern "C" void kernel_launch(void* const* d_in, const int* in_sizes, int n_in,
                              void* d_out, int out_size) {
    const float* fs = (const float*)d_in[0];
    const float* ft = (const float*)d_in[1];
    const float* ls = (const float*)d_in[2];
    const float* lt = (const float*)d_in[3];
    const int*   tg = (const int*)d_in[4];   // int32 or int64 words, detected on-device
    int N = in_sizes[4];
    int C = in_sizes[2] / N;
    int nt = N / TILE;

    cudaFuncSetAttribute(k_gemm, cudaFuncAttributeMaxDynamicSharedMemorySize, SMEM_GEMM);
    cudaFuncSetAttribute(k_pos,  cudaFuncAttributeMaxDynamicSharedMemorySize, SMEM_POS);

    // harness prepends 2 launches; ncu -s 5 profiles overall idx 5 = our idx 3
    k_init<<<(N_MAX + 255) / 256, 256>>>();                    // 0
    k_prep<<<2 * N, D_FIX>>>(fs, ft, N);                       // 1
    k_detect<<<1, 32>>>(tg);                                   // 2
    dim3 grid(nt, nt);
    k_gemm<<<grid, 256, SMEM_GEMM>>>();                        // 3  <- profiled
    k_count<<<(N + 255) / 256, 256>>>(tg, N);                  // 4
    k_scan<<<1, NBINS>>>();                                    // 5
    k_scatter<<<(N + 255) / 256, 256>>>(N);                    // 6
    k_pos<<<NBINS, 128, SMEM_POS>>>(N);                        // 7
    k_jsd<<<N, 256>>>(ls, lt, N, C);                           // 8
    k_final<<<1, 32>>>((float*)d_out);                         // 9
}

// round 16
// speedup vs baseline: 1.3657x; 1.3657x over previous
#include <cuda_runtime.h>
#include <cuda_bf16.h>
#include <cstdint>

// Shapes (fixed by the problem): N=8192 rows, D=128 feat, C=1000 classes.
#define N_MAX 8192
#define D_FIX 128
#define NBINS 1024
#define NCE_INV_T 10.0f
#define EPSV 1e-10f

#define TILE 128
#define ROWE 136                     // padded row stride (elements) -> 272 B
#define TILE_BYTES (TILE * ROWE * 2) // 34816 B per operand tile
#define SMEM_GEMM (2 * TILE_BYTES)   // 69632 B

// ---------------- device scratch (no allocations allowed) ----------------
__device__ float  g_f1[N_MAX * D_FIX];   // normalized fs * 10 (fp32, for k_pos)
__device__ float  g_f2[N_MAX * D_FIX];   // normalized ft (fp32, for k_pos)
__device__ __align__(16) __nv_bfloat16 g_a16[N_MAX * ROWE]; // bf16 A, padded rows
__device__ __align__(16) __nv_bfloat16 g_b16[N_MAX * ROWE]; // bf16 B, padded rows
__device__ float  g_S1[N_MAX], g_S2[N_MAX], g_S3[N_MAX]; // row sums of e, e^2, e^3
__device__ int    g_tgt[N_MAX];
__device__ int    g_cnt[NBINS], g_off[NBINS], g_cur[NBINS];
__device__ int    g_sorted[N_MAX];
__device__ int    g_is64;
__device__ double g_acc;

// ---------------- PTX helpers ----------------
__device__ __forceinline__ uint32_t smem_to_u32(const void* p) {
    uint32_t a;
    asm("{ .reg .u64 t; cvta.to.shared.u64 t, %1; cvt.u32.u64 %0, t; }" : "=r"(a) : "l"(p));
    return a;
}
__device__ __forceinline__ void cp16(uint32_t dst, const void* src) {
    asm volatile("cp.async.cg.shared.global [%0], [%1], 16;" :: "r"(dst), "l"(src) : "memory");
}
__device__ __forceinline__ void ldsm_x4(uint32_t* r, uint32_t addr) {
    asm volatile("ldmatrix.sync.aligned.m8n8.x4.shared.b16 {%0,%1,%2,%3}, [%4];"
                 : "=r"(r[0]), "=r"(r[1]), "=r"(r[2]), "=r"(r[3]) : "r"(addr));
}
__device__ __forceinline__ void mma16816(float* c, const uint32_t* a, const uint32_t* b) {
    asm volatile("mma.sync.aligned.m16n8k16.row.col.f32.bf16.bf16.f32 "
                 "{%0,%1,%2,%3}, {%4,%5,%6,%7}, {%8,%9}, {%0,%1,%2,%3};"
                 : "+f"(c[0]), "+f"(c[1]), "+f"(c[2]), "+f"(c[3])
                 : "r"(a[0]), "r"(a[1]), "r"(a[2]), "r"(a[3]), "r"(b[0]), "r"(b[1]));
}

// ---------------- K0: zero accumulators (fresh every replay) ----------------
__global__ void k_init() {
    int i = blockIdx.x * blockDim.x + threadIdx.x;
    if (i < N_MAX) { g_S1[i] = 0.f; g_S2[i] = 0.f; g_S3[i] = 0.f; }
    if (i < NBINS) { g_cnt[i] = 0; g_cur[i] = 0; }
    if (i == 0) g_acc = 0.0;
}

// ---------------- K0b: detect target dtype (int64 vs int32) ------------------
__global__ void k_detect(const int* __restrict__ w) {
    int nz = 0;
    for (int i = threadIdx.x; i < 64; i += 32)
        if (w[2 * i + 1] != 0) nz = 1;
    #pragma unroll
    for (int o = 16; o; o >>= 1) nz |= __shfl_xor_sync(0xffffffffu, nz, o);
    if (threadIdx.x == 0) g_is64 = nz ? 0 : 1;
}

// ---------------- K1: normalize; fp32 copies + padded bf16 operands ----------
__global__ void k_prep(const float* __restrict__ fs, const float* __restrict__ ft, int N) {
    int row = blockIdx.x;
    bool is_s = (row < N);
    int r = is_s ? row : row - N;
    int k = threadIdx.x;
    const float* src = is_s ? fs : ft;
    float v = src[r * D_FIX + k];
    float ss = v * v;
    #pragma unroll
    for (int o = 16; o; o >>= 1) ss += __shfl_xor_sync(0xffffffffu, ss, o);
    __shared__ float ws[4];
    if ((k & 31) == 0) ws[k >> 5] = ss;
    __syncthreads();
    float tot = ws[0] + ws[1] + ws[2] + ws[3];
    float nrm = fmaxf(sqrtf(tot), 1e-12f);
    float x = v * ((is_s ? NCE_INV_T : 1.0f) / nrm);
    (is_s ? g_f1 : g_f2)[r * D_FIX + k] = x;
    __nv_bfloat16* dst = is_s ? g_a16 : g_b16;
    dst[r * ROWE + k] = __float2bfloat16(x);
    if (k < ROWE - D_FIX) dst[r * ROWE + D_FIX + k] = __float2bfloat16(0.f); // pad
}

// ---------------- K5: bf16 mma.sync GEMM, K-half pipelined --------------------
// 128x128 tile/CTA, 8 warps (4m x 2n), K=128 resident.
// cp.async in TWO commit groups (k columns 0..63, then 64..135) so MMA on the
// first half overlaps the second half's fill.
__global__ __launch_bounds__(256, 2) void k_gemm() {
    extern __shared__ __align__(16) unsigned char smem[];
    uint32_t SAu = smem_to_u32(smem);
    uint32_t SBu = SAu + TILE_BYTES;
    int tid = threadIdx.x, lane = tid & 31, wid = tid >> 5;
    int wm = wid & 3, wn = wid >> 2;
    int row0 = blockIdx.y * TILE, col0 = blockIdx.x * TILE;

    const char* ga = (const char*)(g_a16 + (size_t)row0 * ROWE);
    const char* gb = (const char*)(g_b16 + (size_t)col0 * ROWE);
    // group 0: first 128 B of every row (k = 0..63)
    for (int idx = tid; idx < 128 * 8; idx += 256) {
        int row = idx >> 3, ch = idx & 7;
        int off = row * 272 + ch * 16;
        cp16(SAu + off, ga + off);
        cp16(SBu + off, gb + off);
    }
    asm volatile("cp.async.commit_group;" ::: "memory");
    // group 1: remaining 144 B of every row (k = 64..135 incl pad)
    for (int idx = tid; idx < 128 * 9; idx += 256) {
        int row = idx / 9, ch = idx % 9;
        int off = row * 272 + 128 + ch * 16;
        cp16(SAu + off, ga + off);
        cp16(SBu + off, gb + off);
    }
    asm volatile("cp.async.commit_group;" ::: "memory");

    uint32_t a_base = SAu + (wm * 32 + (lane & 15)) * 272 + (((lane >> 4) & 1) << 3) * 2;
    uint32_t b_base = SBu + (wn * 64 + (((lane >> 4) & 1) << 3) + (lane & 7)) * 272
                          + (((lane >> 3) & 1) << 3) * 2;

    float c[2][8][4];
    #pragma unroll
    for (int mi = 0; mi < 2; mi++)
        #pragma unroll
        for (int ni = 0; ni < 8; ni++)
            #pragma unroll
            for (int j = 0; j < 4; j++) c[mi][ni][j] = 0.f;

    asm volatile("cp.async.wait_group 1;" ::: "memory");  // first half landed
    __syncthreads();
    #pragma unroll
    for (int kb = 0; kb < 64; kb += 16) {
        uint32_t a[2][4], b[8][2];
        #pragma unroll
        for (int mi = 0; mi < 2; mi++)
            ldsm_x4(a[mi], a_base + mi * 16 * 272 + kb * 2);
        #pragma unroll
        for (int p = 0; p < 4; p++) {
            uint32_t r[4];
            ldsm_x4(r, b_base + p * 16 * 272 + kb * 2);
            b[2 * p][0] = r[0]; b[2 * p][1] = r[1];
            b[2 * p + 1][0] = r[2]; b[2 * p + 1][1] = r[3];
        }
        #pragma unroll
        for (int mi = 0; mi < 2; mi++)
            #pragma unroll
            for (int ni = 0; ni < 8; ni++)
                mma16816(c[mi][ni], a[mi], b[ni]);
    }
    asm volatile("cp.async.wait_group 0;" ::: "memory");  // second half landed
    __syncthreads();
    #pragma unroll
    for (int kb = 64; kb < 128; kb += 16) {
        uint32_t a[2][4], b[8][2];
        #pragma unroll
        for (int mi = 0; mi < 2; mi++)
            ldsm_x4(a[mi], a_base + mi * 16 * 272 + kb * 2);
        #pragma unroll
        for (int p = 0; p < 4; p++) {
            uint32_t r[4];
            ldsm_x4(r, b_base + p * 16 * 272 + kb * 2);
            b[2 * p][0] = r[0]; b[2 * p][1] = r[1];
            b[2 * p + 1][0] = r[2]; b[2 * p + 1][1] = r[3];
        }
        #pragma unroll
        for (int mi = 0; mi < 2; mi++)
            #pragma unroll
            for (int ni = 0; ni < 8; ni++)
                mma16816(c[mi][ni], a[mi], b[ni]);
    }

    // epilogue: e = exp(logit); per-row power sums (each thread owns 4 rows)
    float s1[4] = {0, 0, 0, 0}, s2[4] = {0, 0, 0, 0}, s3[4] = {0, 0, 0, 0};
    #pragma unroll
    for (int mi = 0; mi < 2; mi++)
        #pragma unroll
        for (int ni = 0; ni < 8; ni++)
            #pragma unroll
            for (int j = 0; j < 4; j++) {
                float e = __expf(c[mi][ni][j]);
                int idx = mi * 2 + (j >> 1);
                float e2 = e * e;
                s1[idx] += e; s2[idx] += e2; s3[idx] += e2 * e;
            }
    #pragma unroll
    for (int idx = 0; idx < 4; idx++) {
        #pragma unroll
        for (int o = 1; o <= 2; o <<= 1) {
            s1[idx] += __shfl_xor_sync(0xffffffffu, s1[idx], o);
            s2[idx] += __shfl_xor_sync(0xffffffffu, s2[idx], o);
            s3[idx] += __shfl_xor_sync(0xffffffffu, s3[idx], o);
        }
    }
    if ((lane & 3) == 0) {
        int g = lane >> 2;
        #pragma unroll
        for (int idx = 0; idx < 4; idx++) {
            int mi = idx >> 1, half = idx & 1;
            int grow = row0 + wm * 32 + mi * 16 + half * 8 + g;
            atomicAdd(&g_S1[grow], s1[idx]);
            atomicAdd(&g_S2[grow], s2[idx]);
            atomicAdd(&g_S3[grow], s3[idx]);
        }
    }
}

// ---------------- K2: class histogram + dtype-aware load ----------------
__global__ void k_count(const int* __restrict__ w, int N) {
    int i = blockIdx.x * blockDim.x + threadIdx.x;
    if (i < N) {
        int c = g_is64 ? w[2 * i] : w[i];
        if (c < 0 || c >= NBINS) c = 0;
        g_tgt[i] = c;
        atomicAdd(&g_cnt[c], 1);
    }
}

// ---------------- K3: exclusive scan over class counts (1 block) -------------
__global__ void k_scan() {
    __shared__ int s[NBINS];
    int t = threadIdx.x;
    s[t] = g_cnt[t];
    __syncthreads();
    for (int off = 1; off < NBINS; off <<= 1) {
        int v = (t >= off) ? s[t - off] : 0;
        __syncthreads();
        s[t] += v;
        __syncthreads();
    }
    g_off[t] = s[t] - g_cnt[t];
}

// ---------------- K4: scatter row ids grouped by class ----------------
__global__ void k_scatter(int N) {
    int i = blockIdx.x * blockDim.x + threadIdx.x;
    if (i < N) {
        int c = g_tgt[i];
        int p = atomicAdd(&g_cur[c], 1);
        g_sorted[g_off[c] + p] = i;
    }
}

// ---------------- K6: per-ROW pos-pair kernel (R10 formulation) ---------------
// 8192 CTAs; each recomputes its ~82 pos-pair logits exactly.
// -log(1-x) = x + x^2/2 + x^3/3 + O(x^4), ps <= ~0.005:
// sum over ALL j of series = 1 + S2/(2Z^2) + S3/(3Z^3); subtract exact pos part.
__global__ void k_pos(int N) {
    int i = blockIdx.x;
    int tid = threadIdx.x; // 128
    int c = g_tgt[i];
    int pcnt = g_cnt[c];
    int base = g_off[c];
    __shared__ __align__(16) float frow[D_FIX];
    frow[tid] = g_f1[i * D_FIX + tid];
    __syncthreads();
    float invZ = 1.0f / g_S1[i];
    float plog = 0.f, pser = 0.f;
    for (int t = tid; t < pcnt; t += 128) {
        int j = g_sorted[base + t];
        const float4* br = reinterpret_cast<const float4*>(g_f2 + j * D_FIX);
        const float4* ar = reinterpret_cast<const float4*>(frow);
        float dot = 0.f;
        #pragma unroll
        for (int q = 0; q < D_FIX / 4; q++) {
            float4 b4 = br[q], a4 = ar[q];
            dot += a4.x * b4.x + a4.y * b4.y + a4.z * b4.z + a4.w * b4.w;
        }
        float ps = __expf(dot) * invZ;
        plog -= __logf(ps + EPSV);
        pser += ps * (1.0f + ps * (0.5f + ps * (1.0f / 3.0f)));
    }
    #pragma unroll
    for (int o = 16; o; o >>= 1) {
        plog += __shfl_xor_sync(0xffffffffu, plog, o);
        pser += __shfl_xor_sync(0xffffffffu, pser, o);
    }
    __shared__ float r1[4], r2[4];
    if ((tid & 31) == 0) { r1[tid >> 5] = plog; r2[tid >> 5] = pser; }
    __syncthreads();
    if (tid == 0) {
        plog = r1[0] + r1[1] + r1[2] + r1[3];
        pser = r2[0] + r2[1] + r2[2] + r2[3];
        float s2 = g_S2[i] * invZ * invZ;
        float s3 = g_S3[i] * invZ * invZ * invZ;
        float tot = 1.0f + 0.5f * s2 + (1.0f / 3.0f) * s3;
        float negs = tot - pser;
        float row = plog / (float)pcnt + negs / (float)(N - pcnt);
        atomicAdd(&g_acc, (double)row / (double)N);
    }
}

// ---------------- K7: JSD rows, single pass -----------------------------------
// kl_st + kl_ts = sum (pt - ps)(log pt - log ps) = sum (pt - ps)(b - a)
// (log-Z terms cancel since sum(pt - ps) = 0). One pass accumulates
// Zs, Zt, Sds = sum e^a (b-a), Sdt = sum e^b (b-a); kl = Sdt/Zt - Sds/Zs.
__global__ void k_jsd(const float* __restrict__ ls, const float* __restrict__ lt,
                      int N, int C) {
    int i = blockIdx.x;
    int tid = threadIdx.x; // 256
    const float* s = ls + (size_t)i * C;
    const float* t = lt + (size_t)i * C;
    float es = 0.f, et = 0.f, ds = 0.f, dt = 0.f;
    for (int j = tid; j < C; j += 256) {
        float a = s[j], b = t[j];
        float ea = __expf(a), eb = __expf(b);
        float d = b - a;
        es += ea; et += eb;
        ds += ea * d; dt += eb * d;
    }
    #pragma unroll
    for (int o = 16; o; o >>= 1) {
        es += __shfl_xor_sync(0xffffffffu, es, o);
        et += __shfl_xor_sync(0xffffffffu, et, o);
        ds += __shfl_xor_sync(0xffffffffu, ds, o);
        dt += __shfl_xor_sync(0xffffffffu, dt, o);
    }
    __shared__ float w1[8], w2[8], w3[8], w4[8];
    if ((tid & 31) == 0) {
        int w = tid >> 5;
        w1[w] = es; w2[w] = et; w3[w] = ds; w4[w] = dt;
    }
    __syncthreads();
    if (tid == 0) {
        float zs = 0.f, zt = 0.f, sd = 0.f, td = 0.f;
        #pragma unroll
        for (int w = 0; w < 8; w++) { zs += w1[w]; zt += w2[w]; sd += w3[w]; td += w4[w]; }
        float kl = td / zt - sd / zs;
        atomicAdd(&g_acc, 0.5 * (double)kl / (double)N);
    }
}

// ---------------- K8: write scalar output ----------------
__global__ void k_final(float* out) {
    if (threadIdx.x == 0) out[0] = (float)g_acc;
}

// ---------------- launcher ----------------
extern "C" void kernel_launch(void* const* d_in, const int* in_sizes, int n_in,
                              void* d_out, int out_size) {
    const float* fs = (const float*)d_in[0];
    const float* ft = (const float*)d_in[1];
    const float* ls = (const float*)d_in[2];
    const float* lt = (const float*)d_in[3];
    const int*   tg = (const int*)d_in[4];   // int32 or int64 words, detected on-device
    int N = in_sizes[4];
    int C = in_sizes[2] / N;
    int nt = N / TILE;

    cudaFuncSetAttribute(k_gemm, cudaFuncAttributeMaxDynamicSharedMemorySize, SMEM_GEMM);

    // harness prepends 2 launches; ncu -s 5 profiles overall idx 5 = our idx 3
    k_init<<<(N_MAX + 255) / 256, 256>>>();                    // 0
    k_prep<<<2 * N, D_FIX>>>(fs, ft, N);                       // 1
    k_detect<<<1, 32>>>(tg);                                   // 2
    dim3 grid(nt, nt);
    k_gemm<<<grid, 256, SMEM_GEMM>>>();                        // 3  <- profiled
    k_count<<<(N + 255) / 256, 256>>>(tg, N);                  // 4
    k_scan<<<1, NBINS>>>();                                    // 5
    k_scatter<<<(N + 255) / 256, 256>>>(N);                    // 6
    k_pos<<<N, 128>>>(N);                                      // 7
    k_jsd<<<N, 256>>>(ls, lt, N, C);                           // 8
    k_final<<<1, 32>>>((float*)d_out);                         // 9
}